// round 4
// baseline (speedup 1.0000x reference)
#include <cuda_runtime.h>

// GRU fused kernel: B=2048, T=256, F=64, H=32 (gates r,z,n PyTorch order)
// out[b] = sigmoid( h_T[b] @ W_head^T + b_head )

#define Bn 2048
#define Tn 256
#define Fn 64
#define Hn 32
#define ROWS_PER_BLOCK 4
#define NTHREADS (ROWS_PER_BLOCK * 96)   // 3 warps per row

typedef unsigned long long ull;

__device__ __forceinline__ ull fma2(ull a, ull b, ull c) {
    ull d;
    asm("fma.rn.f32x2 %0, %1, %2, %3;" : "=l"(d) : "l"(a), "l"(b), "l"(c));
    return d;
}
__device__ __forceinline__ float lo2(ull v) { return __uint_as_float((unsigned)(v & 0xffffffffull)); }
__device__ __forceinline__ float hi2(ull v) { return __uint_as_float((unsigned)(v >> 32)); }
__device__ __forceinline__ float sum2(ull v) { return lo2(v) + hi2(v); }

__device__ __forceinline__ float fsigmoid(float x) {
    return 1.0f / (1.0f + __expf(-x));
}
__device__ __forceinline__ float ftanh(float x) {
    // overflow-safe tanh via exp of negative magnitude
    float e = __expf(-2.0f * fabsf(x));
    float y = (1.0f - e) / (1.0f + e);
    return copysignf(y, x);
}

__global__ __launch_bounds__(NTHREADS, 1) void gru_fused_kernel(
    const float* __restrict__ x,       // [B,T,F]
    const float* __restrict__ W_ih,    // [96,64]
    const float* __restrict__ W_hh,    // [96,32]
    const float* __restrict__ b_ih,    // [96]
    const float* __restrict__ b_hh,    // [96]
    const float* __restrict__ W_head,  // [1,32]
    const float* __restrict__ b_head,  // [1]
    float* __restrict__ out)           // [B,1]
{
    __shared__ __align__(16) ull   xs[2][ROWS_PER_BLOCK][Fn / 2];  // x pairs, double-buffered
    __shared__ __align__(16) float hs[ROWS_PER_BLOCK][Hn];
    __shared__ float rs[ROWS_PER_BLOCK][Hn];
    __shared__ float zs[ROWS_PER_BLOCK][Hn];

    const int tid  = threadIdx.x;
    const int w    = tid >> 5;
    const int lane = tid & 31;
    const int g    = w % 3;           // gate: 0=r, 1=z, 2=n
    const int rl   = w / 3;           // row within block
    const int row  = blockIdx.x * ROWS_PER_BLOCK + rl;
    const int o    = g * 32 + lane;   // output index in [0,96)

    // ---- register-resident weights, packed as f32 pairs along K ----
    ull wih[Fn / 2];
    {
        const ull* wp = (const ull*)(W_ih + (size_t)o * Fn);
#pragma unroll
        for (int k = 0; k < Fn / 2; k++) wih[k] = wp[k];
    }
    ull whh[Hn / 2];
    {
        const ull* hp = (const ull*)(W_hh + (size_t)o * Hn);
#pragma unroll
        for (int k = 0; k < Hn / 2; k++) whh[k] = hp[k];
    }
    const float bi = b_ih[o];
    const float bh = b_hh[o];

    // ---- init h=0, stage x_0, prefetch x_1 into regs ----
    if (tid < ROWS_PER_BLOCK * Hn) ((float*)hs)[tid] = 0.0f;

    const ull* xrow = (const ull*)(x + (size_t)row * Tn * Fn);  // 32 ull per timestep
    if (g == 0) xs[0][rl][lane] = xrow[lane];                   // t = 0
    ull xpre = 0ull;
    if (g == 0) xpre = xrow[(Fn / 2) + lane];                   // t = 1
    __syncthreads();

    for (int t = 0; t < Tn; t++) {
        const int cur = t & 1;
        const int nxt = cur ^ 1;

        // stage x_{t+1} (loaded last iteration, latency hidden), prefetch x_{t+2}
        if (g == 0 && t + 1 < Tn) {
            xs[nxt][rl][lane] = xpre;
            if (t + 2 < Tn) xpre = xrow[(size_t)(t + 2) * (Fn / 2) + lane];
        }

        // ---- phase 1: xg and hg dot products (packed, 48 FFMA2 per warp) ----
        ull accx = 0ull, acch = 0ull;
        const ull* xb = xs[cur][rl];
#pragma unroll
        for (int k = 0; k < Fn / 2; k++) accx = fma2(xb[k], wih[k], accx);
        const ull* hb = (const ull*)hs[rl];
#pragma unroll
        for (int k = 0; k < Hn / 2; k++) acch = fma2(hb[k], whh[k], acch);

        const float h_old = hs[rl][lane];  // used by g==2 only
        const float xpart = sum2(accx);
        const float hpart = sum2(acch);

        if (g == 0) {
            rs[rl][lane] = fsigmoid(xpart + hpart + bi + bh);
        } else if (g == 1) {
            zs[rl][lane] = fsigmoid(xpart + hpart + bi + bh);
        }
        const float xn = xpart + bi;  // n-gate keeps xn / hn separate (r scales hn only)
        const float hn = hpart + bh;

        __syncthreads();

        // ---- phase 2: n-warp combines gates and updates h ----
        if (g == 2) {
            const float r = rs[rl][lane];
            const float z = zs[rl][lane];
            const float n = ftanh(xn + r * hn);
            hs[rl][lane]  = (1.0f - z) * n + z * h_old;
        }

        __syncthreads();
    }

    // ---- head: y = sigmoid(h_T . W_head + b_head), one warp per row ----
    if (g == 2) {
        float p = hs[rl][lane] * W_head[lane];
#pragma unroll
        for (int s = 16; s > 0; s >>= 1) p += __shfl_xor_sync(0xffffffffu, p, s);
        if (lane == 0) out[row] = fsigmoid(p + b_head[0]);
    }
}

extern "C" void kernel_launch(void* const* d_in, const int* in_sizes, int n_in,
                              void* d_out, int out_size)
{
    const float* x      = (const float*)d_in[0];
    const float* W_ih   = (const float*)d_in[1];
    const float* W_hh   = (const float*)d_in[2];
    const float* b_ih   = (const float*)d_in[3];
    const float* b_hh   = (const float*)d_in[4];
    const float* W_head = (const float*)d_in[5];
    const float* b_head = (const float*)d_in[6];
    float* out          = (float*)d_out;

    gru_fused_kernel<<<Bn / ROWS_PER_BLOCK, NTHREADS>>>(
        x, W_ih, W_hh, b_ih, b_hh, W_head, b_head, out);
}

// round 5
// speedup vs baseline: 2.5216x; 2.5216x over previous
#include <cuda_runtime.h>

// Two-phase GRU: B=2048, T=256, F=64, H=32, gates r,z,n (PyTorch order)
//   K1 xproj:  xg[b,t,o] = x[b,t,:].W_ih[o,:] + bias_o   (bias pre-folded)
//   K2 gru_rec: warp-per-row recurrence + sigmoid head, no block barriers.

#define Bn 2048
#define Tn 256
#define Fn 64
#define Hn 32

#define BT (Bn * Tn)            // 524288 rows
#define TILE_ROWS 64            // rows staged per cp.async tile (16KB)
#define K1_THREADS 256          // 8 warps; warp handles 8 rows/tile
#define K1_BLOCKS 1024
#define TILES_PER_BLOCK (BT / TILE_ROWS / K1_BLOCKS)   // 8

typedef unsigned long long ull;

// 201MB scratch for the input-gate projections, [BT][96] (r|z|n per row)
__device__ float g_xg[(size_t)BT * 96];

__device__ __forceinline__ ull fma2(ull a, ull b, ull c) {
    ull d;
    asm("fma.rn.f32x2 %0, %1, %2, %3;" : "=l"(d) : "l"(a), "l"(b), "l"(c));
    return d;
}
__device__ __forceinline__ float sum2(ull v) {
    return __uint_as_float((unsigned)(v & 0xffffffffull)) +
           __uint_as_float((unsigned)(v >> 32));
}
__device__ __forceinline__ float tanhap(float x) {
    float y;
    asm("tanh.approx.f32 %0, %1;" : "=f"(y) : "f"(x));
    return y;
}
__device__ __forceinline__ float fsig(float x) {           // sigmoid via MUFU.TANH
    return fmaf(tanhap(0.5f * x), 0.5f, 0.5f);
}

__device__ __forceinline__ void cp_async16(void* smem, const void* gmem) {
    unsigned s = (unsigned)__cvta_generic_to_shared(smem);
    asm volatile("cp.async.cg.shared.global [%0], [%1], 16;\n" :: "r"(s), "l"(gmem));
}
__device__ __forceinline__ void cp_commit() { asm volatile("cp.async.commit_group;\n"); }
__device__ __forceinline__ void cp_wait1()  { asm volatile("cp.async.wait_group 1;\n"); }
__device__ __forceinline__ void cp_wait0()  { asm volatile("cp.async.wait_group 0;\n"); }

// ------------------------------------------------------------------ kernel 1
__global__ __launch_bounds__(K1_THREADS, 1) void xproj_kernel(
    const float* __restrict__ x,      // [BT, 64] (flattened [B,T,F])
    const float* __restrict__ W_ih,   // [96, 64]
    const float* __restrict__ b_ih,   // [96]
    const float* __restrict__ b_hh)   // [96]
{
    __shared__ __align__(16) float xt[2][TILE_ROWS][Fn];   // 2 x 16KB

    const int tid  = threadIdx.x;
    const int lane = tid & 31;
    const int w    = tid >> 5;

    // lane owns outputs: lane (r), 32+lane (z), 64+lane (n)
    ull w0[Fn / 2], w1[Fn / 2], w2[Fn / 2];
    {
        const ull* p0 = (const ull*)(W_ih + (size_t)lane * Fn);
        const ull* p1 = (const ull*)(W_ih + (size_t)(32 + lane) * Fn);
        const ull* p2 = (const ull*)(W_ih + (size_t)(64 + lane) * Fn);
#pragma unroll
        for (int k = 0; k < Fn / 2; k++) { w0[k] = p0[k]; w1[k] = p1[k]; w2[k] = p2[k]; }
    }
    const float bias0 = b_ih[lane]      + b_hh[lane];       // r: both biases fold
    const float bias1 = b_ih[32 + lane] + b_hh[32 + lane];  // z: both biases fold
    const float bias2 = b_ih[64 + lane];                    // n: b_hh_n stays in K2

    const int tile0 = blockIdx.x * TILES_PER_BLOCK;
    const float4* xg4 = (const float4*)x;                   // 16 float4 per row

    // stage helper: copy tile (64 rows x 256B = 1024 float4) into buf
    auto stage = [&](int tile, int buf) {
#pragma unroll
        for (int p = 0; p < 4; p++) {
            int i = p * K1_THREADS + tid;                   // 0..1023
            cp_async16(&((float4*)xt[buf])[i], &xg4[(size_t)tile * TILE_ROWS * 16 + i]);
        }
        cp_commit();
    };

    stage(tile0 + 0, 0);
    stage(tile0 + 1, 1);

    for (int t = 0; t < TILES_PER_BLOCK; t++) {
        const int buf = t & 1;
        if (t == TILES_PER_BLOCK - 1) cp_wait0(); else cp_wait1();
        __syncthreads();

        const int tile = tile0 + t;
#pragma unroll 2
        for (int r = 0; r < 8; r++) {
            const int row = w * 8 + r;
            const ulonglong2* xp = (const ulonglong2*)xt[buf][row];  // broadcast reads
            ull a0 = 0ull, a1 = 0ull, a2 = 0ull;
#pragma unroll
            for (int k = 0; k < 16; k++) {
                ulonglong2 v = xp[k];
                a0 = fma2(v.x, w0[2 * k], a0); a0 = fma2(v.y, w0[2 * k + 1], a0);
                a1 = fma2(v.x, w1[2 * k], a1); a1 = fma2(v.y, w1[2 * k + 1], a1);
                a2 = fma2(v.x, w2[2 * k], a2); a2 = fma2(v.y, w2[2 * k + 1], a2);
            }
            float* out = g_xg + (size_t)(tile * TILE_ROWS + row) * 96;
            out[lane]      = sum2(a0) + bias0;
            out[32 + lane] = sum2(a1) + bias1;
            out[64 + lane] = sum2(a2) + bias2;
        }
        __syncthreads();
        if (t + 2 < TILES_PER_BLOCK) stage(tile0 + t + 2, buf);
    }
}

// ------------------------------------------------------------------ kernel 2
__global__ __launch_bounds__(128, 4) void gru_rec_kernel(
    const float* __restrict__ W_hh,    // [96, 32]
    const float* __restrict__ b_hh,    // [96]
    const float* __restrict__ W_head,  // [32]
    const float* __restrict__ b_head,  // [1]
    float* __restrict__ out)           // [B]
{
    __shared__ __align__(16) float hs[2][4][Hn];   // double-buffered h per warp

    const int tid  = threadIdx.x;
    const int lane = tid & 31;
    const int wr   = tid >> 5;
    const int row  = blockIdx.x * 4 + wr;

    ull whr[Hn / 2], whz[Hn / 2], whn[Hn / 2];
    {
        const ull* p0 = (const ull*)(W_hh + (size_t)lane * Hn);
        const ull* p1 = (const ull*)(W_hh + (size_t)(32 + lane) * Hn);
        const ull* p2 = (const ull*)(W_hh + (size_t)(64 + lane) * Hn);
#pragma unroll
        for (int k = 0; k < Hn / 2; k++) { whr[k] = p0[k]; whz[k] = p1[k]; whn[k] = p2[k]; }
    }
    const float bhn = b_hh[64 + lane];

    const float* xp = g_xg + (size_t)row * Tn * 96;
    float h = 0.0f;
    hs[0][wr][lane] = 0.0f;
    __syncwarp();

    float xr = xp[lane], xz = xp[32 + lane], xn = xp[64 + lane];
    int cur = 0;

    for (int t = 0; t < Tn; t++) {
        // prefetch next step's gate inputs (1-step distance hides DRAM)
        float pr = 0.f, pz = 0.f, pn = 0.f;
        if (t + 1 < Tn) {
            const float* q = xp + (size_t)(t + 1) * 96;
            pr = q[lane]; pz = q[32 + lane]; pn = q[64 + lane];
        }

        ull a0 = 0ull, a1 = 0ull, a2 = 0ull;
        const ulonglong2* hp = (const ulonglong2*)hs[cur][wr];  // broadcast reads
#pragma unroll
        for (int k = 0; k < 8; k++) {
            ulonglong2 v = hp[k];
            a0 = fma2(v.x, whr[2 * k], a0); a0 = fma2(v.y, whr[2 * k + 1], a0);
            a1 = fma2(v.x, whz[2 * k], a1); a1 = fma2(v.y, whz[2 * k + 1], a1);
            a2 = fma2(v.x, whn[2 * k], a2); a2 = fma2(v.y, whn[2 * k + 1], a2);
        }
        const float r  = fsig(xr + sum2(a0));          // biases pre-folded in xr
        const float z  = fsig(xz + sum2(a1));
        const float hn = sum2(a2) + bhn;
        const float n  = tanhap(fmaf(r, hn, xn));
        h = fmaf(z, h - n, n);                          // (1-z)n + z h

        cur ^= 1;
        hs[cur][wr][lane] = h;                          // write to other buffer (no WAR)
        __syncwarp();

        xr = pr; xz = pz; xn = pn;
    }

    // head: y = sigmoid(h . W_head + b_head)
    float p = h * W_head[lane];
#pragma unroll
    for (int s = 16; s > 0; s >>= 1) p += __shfl_xor_sync(0xffffffffu, p, s);
    if (lane == 0) out[row] = fsig(p + b_head[0]);
}

// ------------------------------------------------------------------ launch
extern "C" void kernel_launch(void* const* d_in, const int* in_sizes, int n_in,
                              void* d_out, int out_size)
{
    const float* x      = (const float*)d_in[0];
    const float* W_ih   = (const float*)d_in[1];
    const float* W_hh   = (const float*)d_in[2];
    const float* b_ih   = (const float*)d_in[3];
    const float* b_hh   = (const float*)d_in[4];
    const float* W_head = (const float*)d_in[5];
    const float* b_head = (const float*)d_in[6];
    float* out          = (float*)d_out;

    xproj_kernel<<<K1_BLOCKS, K1_THREADS>>>(x, W_ih, b_ih, b_hh);
    gru_rec_kernel<<<Bn / 4, 128>>>(W_hh, b_hh, W_head, b_head, out);
}

// round 6
// speedup vs baseline: 2.6556x; 1.0532x over previous
#include <cuda_runtime.h>

// Two-phase GRU: B=2048, T=256, F=64, H=32, gates r,z,n (PyTorch order)
//   K1 xproj:  xg[bt,o] = x[bt,:].W_ih[o,:] + bias_o   (gate-split warps)
//   K2 gru_rec: 2 rows per warp, distance-2 prefetch, no block barriers.

#define Bn 2048
#define Tn 256
#define Fn 64
#define Hn 32
#define BT (Bn * Tn)                 // 524288 rows

#define XP_THREADS 192               // 6 warps = 2 row-groups x 3 gates
#define XP_TILE 64                   // rows per cp.async tile (16KB)
#define XP_BLOCKS 1024
#define XP_TPB (BT / XP_TILE / XP_BLOCKS)   // 8 tiles per block

typedef unsigned long long ull;

// 201MB scratch: [BT][96] fp32 (r|z|n, biases pre-folded for r,z; b_ih for n)
__device__ float g_xg[(size_t)BT * 96];

__device__ __forceinline__ ull fma2(ull a, ull b, ull c) {
    ull d;
    asm("fma.rn.f32x2 %0, %1, %2, %3;" : "=l"(d) : "l"(a), "l"(b), "l"(c));
    return d;
}
__device__ __forceinline__ float sum2(ull v) {
    return __uint_as_float((unsigned)(v & 0xffffffffull)) +
           __uint_as_float((unsigned)(v >> 32));
}
__device__ __forceinline__ float tanhap(float x) {
    float y;
    asm("tanh.approx.f32 %0, %1;" : "=f"(y) : "f"(x));
    return y;
}
__device__ __forceinline__ float fsig(float x) {
    return fmaf(tanhap(0.5f * x), 0.5f, 0.5f);
}
__device__ __forceinline__ void cp_async16(void* smem, const void* gmem) {
    unsigned s = (unsigned)__cvta_generic_to_shared(smem);
    asm volatile("cp.async.cg.shared.global [%0], [%1], 16;\n" :: "r"(s), "l"(gmem));
}
__device__ __forceinline__ void cp_commit() { asm volatile("cp.async.commit_group;\n"); }
__device__ __forceinline__ void cp_wait1()  { asm volatile("cp.async.wait_group 1;\n"); }
__device__ __forceinline__ void cp_wait0()  { asm volatile("cp.async.wait_group 0;\n"); }

// ------------------------------------------------------------------ kernel 1
// Gate-split: warp g = w%3 computes outputs [g*32, g*32+32) for its row set.
// 64 weight regs per lane -> no spills, 3 blocks/SM.
__global__ __launch_bounds__(XP_THREADS, 2) void xproj_kernel(
    const float* __restrict__ x,      // [BT, 64]
    const float* __restrict__ W_ih,   // [96, 64]
    const float* __restrict__ b_ih,   // [96]
    const float* __restrict__ b_hh)   // [96]
{
    __shared__ __align__(16) float xt[2][XP_TILE][Fn];   // 2 x 16KB

    const int tid  = threadIdx.x;
    const int lane = tid & 31;
    const int w    = tid >> 5;
    const int g    = w % 3;          // gate
    const int grp  = w / 3;          // row half: 0 or 1
    const int o    = g * 32 + lane;  // output column

    // one W_ih row per lane, packed as f32 pairs (32 ull = 64 regs)
    ull wk[Fn / 2];
    {
        const ull* p = (const ull*)(W_ih + (size_t)o * Fn);
#pragma unroll
        for (int k = 0; k < Fn / 2; k++) wk[k] = p[k];
    }
    const float bias = b_ih[o] + ((g < 2) ? b_hh[o] : 0.0f);

    const int tile0 = blockIdx.x * XP_TPB;
    const float4* x4 = (const float4*)x;       // 16 float4 per row

    auto stage = [&](int tile, int buf) {
        float4* dst = (float4*)xt[buf];
        const float4* src = x4 + (size_t)tile * XP_TILE * 16;
        for (int i = tid; i < XP_TILE * 16; i += XP_THREADS)
            cp_async16(&dst[i], &src[i]);
        cp_commit();
    };

    stage(tile0 + 0, 0);
    stage(tile0 + 1, 1);

    for (int t = 0; t < XP_TPB; t++) {
        const int buf = t & 1;
        if (t == XP_TPB - 1) cp_wait0(); else cp_wait1();
        __syncthreads();

        const int tile = tile0 + t;
        const int rbase = grp * (XP_TILE / 2);
#pragma unroll 2
        for (int r = 0; r < XP_TILE / 2; r++) {
            const int row = rbase + r;
            const ulonglong2* xp = (const ulonglong2*)xt[buf][row];  // broadcast
            ull a = 0ull, b = 0ull;   // two chains for ILP
#pragma unroll
            for (int k = 0; k < 8; k++) {
                ulonglong2 v = xp[k];
                a = fma2(v.x, wk[2 * k], a);
                a = fma2(v.y, wk[2 * k + 1], a);
            }
#pragma unroll
            for (int k = 8; k < 16; k++) {
                ulonglong2 v = xp[k];
                b = fma2(v.x, wk[2 * k], b);
                b = fma2(v.y, wk[2 * k + 1], b);
            }
            g_xg[(size_t)(tile * XP_TILE + row) * 96 + o] = sum2(a) + sum2(b) + bias;
        }
        __syncthreads();
        if (t + 2 < XP_TPB) stage(tile0 + t + 2, buf);
    }
}

// ------------------------------------------------------------------ kernel 2
// One warp handles TWO rows with the same register-resident W_hh (weights are
// lane-indexed only). Distance-2 prefetch of xg -> 12 outstanding LDGs/warp.
__global__ __launch_bounds__(128, 3) void gru_rec_kernel(
    const float* __restrict__ W_hh,    // [96, 32]
    const float* __restrict__ b_hh,    // [96]
    const float* __restrict__ W_head,  // [32]
    const float* __restrict__ b_head,  // [1]
    float* __restrict__ out)           // [B]
{
    __shared__ __align__(16) float hs[2][8][Hn];

    const int tid  = threadIdx.x;
    const int lane = tid & 31;
    const int wr   = tid >> 5;
    const int r0s  = wr * 2;            // shared slot of row0
    const int row0 = blockIdx.x * 8 + r0s;
    const int row1 = row0 + 1;

    ull whr[Hn / 2], whz[Hn / 2], whn[Hn / 2];
    {
        const ull* p0 = (const ull*)(W_hh + (size_t)lane * Hn);
        const ull* p1 = (const ull*)(W_hh + (size_t)(32 + lane) * Hn);
        const ull* p2 = (const ull*)(W_hh + (size_t)(64 + lane) * Hn);
#pragma unroll
        for (int k = 0; k < Hn / 2; k++) { whr[k] = p0[k]; whz[k] = p1[k]; whn[k] = p2[k]; }
    }
    const float bhn = b_hh[64 + lane];

    const float* xp0 = g_xg + (size_t)row0 * Tn * 96;
    const float* xp1 = g_xg + (size_t)row1 * Tn * 96;

    float h0 = 0.0f, h1 = 0.0f;
    hs[0][r0s][lane] = 0.0f;
    hs[0][r0s + 1][lane] = 0.0f;
    __syncwarp();

    // rotating prefetch regs: a = x(t), b = x(t+1); c loads x(t+2)
    float a0r = xp0[lane], a0z = xp0[32 + lane], a0n = xp0[64 + lane];
    float a1r = xp1[lane], a1z = xp1[32 + lane], a1n = xp1[64 + lane];
    float b0r = xp0[96 + lane], b0z = xp0[128 + lane], b0n = xp0[160 + lane];
    float b1r = xp1[96 + lane], b1z = xp1[128 + lane], b1n = xp1[160 + lane];

    int buf = 0;
#pragma unroll 2
    for (int t = 0; t < Tn; t++) {
        // issue loads for t+2 (distance-2: ~2 full steps to cover DRAM latency)
        float c0r = 0.f, c0z = 0.f, c0n = 0.f, c1r = 0.f, c1z = 0.f, c1n = 0.f;
        if (t + 2 < Tn) {
            const float* q0 = xp0 + (size_t)(t + 2) * 96;
            const float* q1 = xp1 + (size_t)(t + 2) * 96;
            c0r = q0[lane]; c0z = q0[32 + lane]; c0n = q0[64 + lane];
            c1r = q1[lane]; c1z = q1[32 + lane]; c1n = q1[64 + lane];
        }

        // row0 + row1 dot products (6 independent FFMA2 chains)
        const ulonglong2* hp0 = (const ulonglong2*)hs[buf][r0s];
        const ulonglong2* hp1 = (const ulonglong2*)hs[buf][r0s + 1];
        ull A0 = 0ull, A1 = 0ull, A2 = 0ull;
        ull B0 = 0ull, B1 = 0ull, B2 = 0ull;
#pragma unroll
        for (int k = 0; k < 8; k++) {
            ulonglong2 u = hp0[k];
            ulonglong2 v = hp1[k];
            A0 = fma2(u.x, whr[2 * k], A0); A0 = fma2(u.y, whr[2 * k + 1], A0);
            A1 = fma2(u.x, whz[2 * k], A1); A1 = fma2(u.y, whz[2 * k + 1], A1);
            A2 = fma2(u.x, whn[2 * k], A2); A2 = fma2(u.y, whn[2 * k + 1], A2);
            B0 = fma2(v.x, whr[2 * k], B0); B0 = fma2(v.y, whr[2 * k + 1], B0);
            B1 = fma2(v.x, whz[2 * k], B1); B1 = fma2(v.y, whz[2 * k + 1], B1);
            B2 = fma2(v.x, whn[2 * k], B2); B2 = fma2(v.y, whn[2 * k + 1], B2);
        }

        {
            const float r = fsig(a0r + sum2(A0));
            const float z = fsig(a0z + sum2(A1));
            const float hn = sum2(A2) + bhn;
            const float n = tanhap(fmaf(r, hn, a0n));
            h0 = fmaf(z, h0 - n, n);
        }
        {
            const float r = fsig(a1r + sum2(B0));
            const float z = fsig(a1z + sum2(B1));
            const float hn = sum2(B2) + bhn;
            const float n = tanhap(fmaf(r, hn, a1n));
            h1 = fmaf(z, h1 - n, n);
        }

        buf ^= 1;
        hs[buf][r0s][lane] = h0;
        hs[buf][r0s + 1][lane] = h1;
        __syncwarp();

        // rotate prefetch regs
        a0r = b0r; a0z = b0z; a0n = b0n;  b0r = c0r; b0z = c0z; b0n = c0n;
        a1r = b1r; a1z = b1z; a1n = b1n;  b1r = c1r; b1z = c1z; b1n = c1n;
    }

    // head: y = sigmoid(h . W_head + b_head)
    const float wh = W_head[lane];
    float p0 = h0 * wh, p1 = h1 * wh;
#pragma unroll
    for (int s = 16; s > 0; s >>= 1) {
        p0 += __shfl_xor_sync(0xffffffffu, p0, s);
        p1 += __shfl_xor_sync(0xffffffffu, p1, s);
    }
    if (lane == 0) {
        const float bh = b_head[0];
        out[row0] = fsig(p0 + bh);
        out[row1] = fsig(p1 + bh);
    }
}

// ------------------------------------------------------------------ launch
extern "C" void kernel_launch(void* const* d_in, const int* in_sizes, int n_in,
                              void* d_out, int out_size)
{
    const float* x      = (const float*)d_in[0];
    const float* W_ih   = (const float*)d_in[1];
    const float* W_hh   = (const float*)d_in[2];
    const float* b_ih   = (const float*)d_in[3];
    const float* b_hh   = (const float*)d_in[4];
    const float* W_head = (const float*)d_in[5];
    const float* b_head = (const float*)d_in[6];
    float* out          = (float*)d_out;

    xproj_kernel<<<XP_BLOCKS, XP_THREADS>>>(x, W_ih, b_ih, b_hh);
    gru_rec_kernel<<<Bn / 8, 128>>>(W_hh, b_hh, W_head, b_head, out);
}